// round 6
// baseline (speedup 1.0000x reference)
#include <cuda_runtime.h>
#include <math.h>

// Problem constants
#define CC      512
#define BB      16
#define TT      60
#define NP      196
#define NHEADS  4
#define HD      128
#define CLIPL   6
#define NFRAMES 36
#define TOPK    6
#define TOPM    12

// Output layout (flat float32):
//   [0]       audio_top_k        (16,36,512)
//   [294912]  visual_patch_top_m (16,36,12,512)
//   [3833856] visual_patch_feat  (16,432,512)  (identical bytes)
#define OFF1 294912
#define OFF2 3833856

// k_qr block roles
#define NB_R      64     // 4 heads x 16 col-slices (each recomputes its head's q)
#define NB_AUDIO  72     // audio gather, 8 (b,f) rows each
#define NB_PREF   24     // L2 prefetch of score-phase patch rows (400KB)
#define NB_QR     (NB_R + NB_AUDIO + NB_PREF)   // 160

// Scratch (device globals)
__device__ float g_r[NHEADS * CC];
__device__ int   g_pid;

// ===========================================================================
// K1: fused q+r (redundant q per block, wide) + audio gather + L2 prefetch
// ===========================================================================
__global__ void __launch_bounds__(256)
k_qr(const float* __restrict__ audio,
     const float* __restrict__ patch,
     const float* __restrict__ qst,
     const int*   __restrict__ topk,
     const float* __restrict__ in_w,
     const float* __restrict__ in_b,
     float*       __restrict__ out) {
    const int bid  = blockIdx.x;
    const int t    = threadIdx.x;
    const int warp = t >> 5, lane = t & 31;

    // ----------------- r blocks: recompute q_h, then 32-col r slice --------
    if (bid < NB_R) {
        __shared__ float sh_q[HD];
        __shared__ float sh_p[8][32];
        const int h  = bid >> 4;            // head 0..3
        const int cb = (bid & 15) * 32;     // col base

        // Phase A: q_h[128] (8 warps x 16 rows, 4 rows in flight for ILP)
        const float4* x4 = (const float4*)qst;     // batch 0
        float4 xv[4];
        #pragma unroll
        for (int i = 0; i < 4; i++) xv[i] = x4[lane + 32 * i];

        #pragma unroll
        for (int rr0 = 0; rr0 < 16; rr0 += 4) {
            float a[4] = {0.f, 0.f, 0.f, 0.f};
            const int row0 = h * HD + warp * 16 + rr0;
            #pragma unroll
            for (int rr = 0; rr < 4; rr++) {
                const float4* w4 = (const float4*)(in_w + (size_t)(row0 + rr) * CC);
                #pragma unroll
                for (int i = 0; i < 4; i++) {
                    float4 w = w4[lane + 32 * i];
                    a[rr] += w.x * xv[i].x + w.y * xv[i].y +
                             w.z * xv[i].z + w.w * xv[i].w;
                }
            }
            #pragma unroll
            for (int rr = 0; rr < 4; rr++) {
                #pragma unroll
                for (int o = 16; o; o >>= 1)
                    a[rr] += __shfl_down_sync(0xffffffffu, a[rr], o);
            }
            if (lane == 0) {
                #pragma unroll
                for (int rr = 0; rr < 4; rr++)
                    sh_q[warp * 16 + rr0 + rr] = a[rr] + in_b[row0 + rr];
            }
        }
        __syncthreads();

        // Phase B: r_h[cb+lane] — j split across warps (16 each, MLP 16)
        const float* Wk = in_w + (size_t)(CC + h * HD + warp * 16) * CC + cb + lane;
        float acc = 0.f;
        #pragma unroll
        for (int j = 0; j < 16; j++)
            acc += Wk[(size_t)j * CC] * sh_q[warp * 16 + j];
        sh_p[warp][lane] = acc;
        __syncthreads();

        if (t < 32) {
            float s = 0.f;
            #pragma unroll
            for (int w = 0; w < 8; w++) s += sh_p[w][t];
            g_r[h * CC + cb + t] = s;
        }
        return;
    }

    // ----------------- audio gather (pid-independent) ----------------------
    if (bid < NB_R + NB_AUDIO) {
        const int ab = bid - NB_R;
        const int tt = t;                       // 0..255: 2 bf rows per iter
        const float4* a4 = (const float4*)audio;
        float4*       o4 = (float4*)out;
        #pragma unroll
        for (int k = 0; k < 4; k++) {
            const int bf = ab * 8 + k * 2 + (tt >> 7);
            const int tl = tt & 127;
            const int b = bf / NFRAMES, f = bf % NFRAMES;
            const int seg   = topk[b * TOPK + f / CLIPL];
            const int frame = seg * CLIPL + (f % CLIPL);
            o4[(size_t)bf * 128 + tl] = a4[((size_t)b * TT + frame) * 128 + tl];
        }
        return;
    }

    // ----------------- prefetch: score-phase patch rows (400KB) ------------
    {
        const int pb  = bid - NB_R - NB_AUDIO;         // 0..23
        const int tid = pb * 256 + t;                  // 0..6143
        const int f0 = topk[0] * CLIPL;
        const char* pr = (const char*)(patch + (size_t)f0 * NP * CC);
        // 196*512*4B = 3136 x 128B lines
        if (tid < 3136)
            asm volatile("prefetch.global.L2 [%0];" :: "l"(pr + (size_t)tid * 128));
    }
}

// ===========================================================================
// K2: scores (196 x 4 heads) + softmax + top-12 select + bcast-row prefetch
// ===========================================================================
__global__ void __launch_bounds__(1024)
k_scorepid(const float* __restrict__ patch, const int* __restrict__ topk) {
    __shared__ float sh_r[NHEADS * CC];
    __shared__ float s_sc[NHEADS * NP];
    __shared__ float s_w[NP];
    __shared__ float s_mx[NHEADS], s_inv[NHEADS];
    __shared__ int   s_pid;

    const int t = threadIdx.x;
    const int warp = t >> 5, lane = t & 31;

    sh_r[t] = g_r[t];
    sh_r[t + 1024] = g_r[t + 1024];
    if (t == 0) s_pid = -1;
    __syncthreads();

    // scores: warp per patch, strided over 32 warps (L2-warm)
    const int f0 = topk[0] * CLIPL;
    const float4* p4 = (const float4*)(patch + (size_t)f0 * NP * CC);
    const float4* r4 = (const float4*)sh_r;
    for (int n = warp; n < NP; n += 32) {
        float4 xvv[4];
        #pragma unroll
        for (int i = 0; i < 4; i++) xvv[i] = p4[(size_t)n * 128 + lane + 32 * i];
        float acc[NHEADS] = {0.f, 0.f, 0.f, 0.f};
        #pragma unroll
        for (int h = 0; h < NHEADS; h++)
            #pragma unroll
            for (int i = 0; i < 4; i++) {
                float4 rv = r4[h * 128 + lane + 32 * i];
                acc[h] += rv.x * xvv[i].x + rv.y * xvv[i].y +
                          rv.z * xvv[i].z + rv.w * xvv[i].w;
            }
        #pragma unroll
        for (int h = 0; h < NHEADS; h++) {
            float v = acc[h];
            #pragma unroll
            for (int o = 16; o; o >>= 1) v += __shfl_down_sync(0xffffffffu, v, o);
            if (lane == 0) s_sc[h * NP + n] = 0.08838834764831845f * v;
        }
    }
    __syncthreads();

    // per-head softmax stats (warp per head)
    if (warp < NHEADS) {
        float m = -1e30f;
        for (int n = lane; n < NP; n += 32) m = fmaxf(m, s_sc[warp * NP + n]);
        #pragma unroll
        for (int o = 16; o; o >>= 1) m = fmaxf(m, __shfl_xor_sync(0xffffffffu, m, o));
        float s = 0.f;
        for (int n = lane; n < NP; n += 32) s += expf(s_sc[warp * NP + n] - m);
        #pragma unroll
        for (int o = 16; o; o >>= 1) s += __shfl_xor_sync(0xffffffffu, s, o);
        if (lane == 0) { s_mx[warp] = m; s_inv[warp] = 1.f / s; }
    }
    __syncthreads();

    // mean-over-heads softmax weights
    if (t < NP) {
        float acc = 0.f;
        #pragma unroll
        for (int h = 0; h < NHEADS; h++)
            acc += expf(s_sc[h * NP + t] - s_mx[h]) * s_inv[h];
        s_w[t] = acc * 0.25f;
    }
    __syncthreads();

    // pid = max index among top-12 (stable-argsort tie-break)
    if (t < NP) {
        const float wn = s_w[t];
        int cnt = 0;
        for (int m = 0; m < NP; m++)
            cnt += (s_w[m] > wn) || (s_w[m] == wn && m > t);
        if (cnt < TOPM) atomicMax(&s_pid, t);
    }
    __syncthreads();
    if (t == 0) g_pid = s_pid;
    __syncthreads();

    // prefetch the 576 bcast source rows (1.15MB) into L2 for k_bcast
    {
        const int pid = s_pid;
        for (int idx = t; idx < 576 * 16; idx += 1024) {
            const int bf = idx >> 4, line = idx & 15;
            const int b = bf / NFRAMES, f = bf % NFRAMES;
            const int seg   = topk[b * TOPK + f / CLIPL];
            const int frame = seg * CLIPL + (f % CLIPL);
            const char* p = (const char*)(patch +
                (((size_t)b * TT + frame) * NP + pid) * CC) + (size_t)line * 128;
            asm volatile("prefetch.global.L2 [%0];" :: "l"(p));
        }
    }
}

// ===========================================================================
// K3: pid-dependent broadcast.  1152 blocks = (bf, region); 12 stores/thread.
// ===========================================================================
__global__ void __launch_bounds__(128)
k_bcast(const float* __restrict__ patch, const int* __restrict__ topk,
        float* __restrict__ out) {
    const int bf  = blockIdx.x >> 1;        // 0..575
    const int reg = blockIdx.x & 1;         // 0 = top_m, 1 = feat
    const int t   = threadIdx.x;            // 0..127
    const int b = bf / NFRAMES, f = bf % NFRAMES;
    const int seg   = topk[b * TOPK + f / CLIPL];
    const int frame = seg * CLIPL + (f % CLIPL);
    const int pid = g_pid;

    const float4* p4 = (const float4*)patch;
    float4*       o4 = (float4*)out;
    const float4 p = p4[(((size_t)b * TT + frame) * NP + pid) * 128 + t];

    const size_t base = (reg ? OFF2 : OFF1) / 4 + (size_t)bf * TOPM * 128 + t;
    #pragma unroll
    for (int m = 0; m < TOPM; m++)
        o4[base + (size_t)m * 128] = p;
}

// ---------------------------------------------------------------------------
extern "C" void kernel_launch(void* const* d_in, const int* in_sizes, int n_in,
                              void* d_out, int out_size) {
    const float* audio = (const float*)d_in[0];   // (16,60,512)
    const float* patch = (const float*)d_in[1];   // (16,60,196,512)
    const float* qst   = (const float*)d_in[2];   // (16,512)
    const int*   topk  = (const int*)  d_in[3];   // (16,1,6)
    const float* in_w  = (const float*)d_in[4];   // (1536,512)
    const float* in_b  = (const float*)d_in[5];   // (1536,)
    float* out = (float*)d_out;

    k_qr<<<NB_QR, 256>>>(audio, patch, qst, topk, in_w, in_b, out);
    k_scorepid<<<1, 1024>>>(patch, topk);
    k_bcast<<<2 * BB * NFRAMES, 128>>>(patch, topk, out);
}